// round 4
// baseline (speedup 1.0000x reference)
#include <cuda_runtime.h>

#define Bv 8192
#define Nv 256
#define Dv 6
#define Rv 3
#define Hv 32

// packed weights: [role][h][8] = {W1 d0..d5, b1[h], W2[h]}, role stride 264 words
#define RSTRIDE 264
__device__ __align__(16) float g_pack[Rv * RSTRIDE];
__device__ float g_b2[Rv];
__device__ int   g_mask_is_u8;   // 0 = int32 mask, 1 = uint8 mask

__global__ void prep_kernel(const float* __restrict__ W1,
                            const float* __restrict__ b1,
                            const float* __restrict__ W2,
                            const float* __restrict__ b2,
                            const unsigned int* __restrict__ mw) {
    __shared__ int any_gt1;
    const int t = threadIdx.x;
    if (t == 0) any_gt1 = 0;
    __syncthreads();

    // mask dtype detection: 4096 words is in-bounds under both layouts
    int found = 0;
    for (int i = t; i < 4096; i += blockDim.x)
        if (mw[i] > 1u) found = 1;
    if (found) any_gt1 = 1;
    __syncthreads();
    if (t == 0) g_mask_is_u8 = any_gt1;

    // weight repack: one (role, h) pair per thread
    if (t < Rv * Hv) {
        const int r = t / Hv, h = t % Hv;
        float* dst = g_pack + r * RSTRIDE + h * 8;
        #pragma unroll
        for (int d = 0; d < Dv; d++) dst[d] = W1[r * Dv * Hv + d * Hv + h];
        dst[6] = b1[r * Hv + h];
        dst[7] = W2[r * Hv + h];
    }
    if (t < Rv) g_b2[t] = b2[t];
}

__global__ __launch_bounds__(Nv, 3)
void hmf_encoder_kernel(const float* __restrict__ states,
                        const int*   __restrict__ roles,
                        const void*  __restrict__ maskp,
                        const float* __restrict__ trust,
                        float* __restrict__ out)
{
    __shared__ float sxT[Dv * Nv];   // transposed state tile: sxT[d*256 + n]
    __shared__ float s_e[Nv];
    __shared__ float s_ew[Nv];
    __shared__ int   s_role[Nv];
    __shared__ float warp_max[8][3];
    __shared__ float sm[Rv];

    const int b    = blockIdx.x;
    const int tid  = threadIdx.x;
    const int lane = tid & 31;
    const int wid  = tid >> 5;
    const size_t base = (size_t)b * Nv;

    // ---- stage state tile transposed (coalesced global read, scattered STS) ----
    {
        const float4* xb4 = (const float4*)(states + base * Dv);
        #pragma unroll
        for (int v = tid; v < (Nv * Dv) / 4; v += Nv) {
            const float4 val = xb4[v];
            const int f0 = v * 4;
            sxT[(f0 % Dv) * Nv + f0 / Dv]             = val.x;
            sxT[((f0 + 1) % Dv) * Nv + (f0 + 1) / Dv] = val.y;
            sxT[((f0 + 2) % Dv) * Nv + (f0 + 2) / Dv] = val.z;
            sxT[((f0 + 3) % Dv) * Nv + (f0 + 3) / Dv] = val.w;
        }
    }
    __syncthreads();

    // ---- per-neighbor loads ----
    const int role = roles[base + tid];
    int mk;
    if (g_mask_is_u8) mk = ((const unsigned char*)maskp)[base + tid];
    else              mk = ((const int*)maskp)[base + tid];
    const bool act = (mk != 0);
    const float twv = act ? trust[base + tid] : 0.0f;

    float xr[Dv];
    #pragma unroll
    for (int d = 0; d < Dv; d++) xr[d] = sxT[d * Nv + tid];   // conflict-free

    // ---- tiny MLP for this neighbor's own role (weights via L1-cached LDG) ----
    float score;
    {
        const float4* wp = (const float4*)(g_pack + role * RSTRIDE);
        float acc0 = 0.0f, acc1 = 0.0f;
        #pragma unroll
        for (int h = 0; h < Hv; h += 2) {
            const float4 a0 = __ldg(wp + h * 2);
            const float4 c0 = __ldg(wp + h * 2 + 1);
            const float4 a1 = __ldg(wp + h * 2 + 2);
            const float4 c1 = __ldg(wp + h * 2 + 3);
            float hv0 = fmaf(xr[0], a0.x, fmaf(xr[1], a0.y,
                        fmaf(xr[2], a0.z, fmaf(xr[3], a0.w,
                        fmaf(xr[4], c0.x, fmaf(xr[5], c0.y, c0.z))))));
            float hv1 = fmaf(xr[0], a1.x, fmaf(xr[1], a1.y,
                        fmaf(xr[2], a1.z, fmaf(xr[3], a1.w,
                        fmaf(xr[4], c1.x, fmaf(xr[5], c1.y, c1.z))))));
            acc0 = fmaf(fmaxf(hv0, 0.0f), c0.w, acc0);
            acc1 = fmaf(fmaxf(hv1, 0.0f), c1.w, acc1);
        }
        const float acc = acc0 + acc1 + __ldg(&g_b2[role]);
        score = act ? acc : 0.0f;   // == scores * role_mask at (n, own role)
    }

    // ---- per-role max over masked scores (zeros included, per reference) ----
    float vm0 = 0.0f, vm1 = 0.0f, vm2 = 0.0f;
    if (act) {
        if (role == 0)      vm0 = score;
        else if (role == 1) vm1 = score;
        else                vm2 = score;
    }
    #pragma unroll
    for (int o = 16; o; o >>= 1) {
        vm0 = fmaxf(vm0, __shfl_xor_sync(0xffffffffu, vm0, o));
        vm1 = fmaxf(vm1, __shfl_xor_sync(0xffffffffu, vm1, o));
        vm2 = fmaxf(vm2, __shfl_xor_sync(0xffffffffu, vm2, o));
    }
    if (lane == 0) {
        warp_max[wid][0] = vm0;
        warp_max[wid][1] = vm1;
        warp_max[wid][2] = vm2;
    }
    __syncthreads();
    if (tid < Rv) {
        float m = warp_max[0][tid];
        #pragma unroll
        for (int w = 1; w < 8; w++) m = fmaxf(m, warp_max[w][tid]);
        sm[tid] = m;
    }
    __syncthreads();

    // ---- exponentials ----
    const float e = act ? __expf(score - sm[role]) : 0.0f;
    s_e[tid]  = e;
    s_ew[tid] = e * twv;
    s_role[tid] = role;
    __syncthreads();

    // ---- warps 0..2: per-role den / wsum / num[6] reductions (all stride-1) ----
    if (wid < Rv) {
        const int r = wid;
        float den = 0.0f, ws = 0.0f;
        float num[Dv] = {0.f, 0.f, 0.f, 0.f, 0.f, 0.f};
        #pragma unroll
        for (int i = 0; i < Nv / 32; i++) {
            const int n = lane + i * 32;
            if (s_role[n] == r) {
                const float ev  = s_e[n];
                const float ewv = s_ew[n];
                den += ev;
                ws  += ewv;
                #pragma unroll
                for (int d = 0; d < Dv; d++)
                    num[d] = fmaf(ewv, sxT[d * Nv + n], num[d]);
            }
        }
        #pragma unroll
        for (int o = 16; o; o >>= 1) {
            den += __shfl_xor_sync(0xffffffffu, den, o);
            ws  += __shfl_xor_sync(0xffffffffu, ws,  o);
            #pragma unroll
            for (int d = 0; d < Dv; d++)
                num[d] += __shfl_xor_sync(0xffffffffu, num[d], o);
        }
        if (lane < Dv) {
            const float inv = 1.0f / (den + 1e-8f);
            const float wsv = fmaxf(ws * inv, 1e-8f);
            out[(size_t)b * (Rv * Dv) + r * Dv + lane] = num[lane] * inv / wsv;
        }
    }
}

extern "C" void kernel_launch(void* const* d_in, const int* in_sizes, int n_in,
                              void* d_out, int out_size) {
    const float* states = (const float*)d_in[0];
    const int*   roles  = (const int*)d_in[1];
    const void*  maskp  = d_in[2];
    const float* trust  = (const float*)d_in[3];
    const float* W1     = (const float*)d_in[4];
    const float* b1     = (const float*)d_in[5];
    const float* W2     = (const float*)d_in[6];
    const float* b2     = (const float*)d_in[7];
    float* out = (float*)d_out;

    prep_kernel<<<1, 256>>>(W1, b1, W2, b2, (const unsigned int*)maskp);
    hmf_encoder_kernel<<<Bv, Nv>>>(states, roles, maskp, trust, out);
}

// round 5
// speedup vs baseline: 1.5724x; 1.5724x over previous
#include <cuda_runtime.h>

#define Bv 8192
#define Nv 256
#define Dv 6
#define Rv 3
#define Hv 32

// packed weights: [role][h][8] = {W1 d0..d5, b1[h], W2[h]}, role stride 264 words
#define RSTRIDE 264
__device__ __align__(16) float g_pack[Rv * RSTRIDE];
__device__ float g_b2[Rv];
__device__ int   g_mask_is_u8;   // 0 = int32 mask, 1 = uint8 mask

__global__ void prep_kernel(const float* __restrict__ W1,
                            const float* __restrict__ b1,
                            const float* __restrict__ W2,
                            const float* __restrict__ b2,
                            const unsigned int* __restrict__ mw) {
    __shared__ int any_gt1;
    const int t = threadIdx.x;
    if (t == 0) any_gt1 = 0;
    __syncthreads();
    int found = 0;
    for (int i = t; i < 4096; i += blockDim.x)   // in-bounds under both mask layouts
        if (mw[i] > 1u) found = 1;
    if (found) any_gt1 = 1;
    __syncthreads();
    if (t == 0) g_mask_is_u8 = any_gt1;

    if (t < Rv * Hv) {
        const int r = t / Hv, h = t % Hv;
        float* dst = g_pack + r * RSTRIDE + h * 8;
        #pragma unroll
        for (int d = 0; d < Dv; d++) dst[d] = W1[r * Dv * Hv + d * Hv + h];
        dst[6] = b1[r * Hv + h];
        dst[7] = W2[r * Hv + h];
    }
    if (t < Rv) g_b2[t] = b2[t];
}

__global__ __launch_bounds__(Nv, 3)
void hmf_encoder_kernel(const float* __restrict__ states,
                        const int*   __restrict__ roles,
                        const void*  __restrict__ maskp,
                        const float* __restrict__ trust,
                        float* __restrict__ out)
{
    __shared__ __align__(16) float sPack[Rv * RSTRIDE];
    __shared__ float sb2[Rv];
    __shared__ __align__(16) float sx[Nv * Dv];   // original order, row-major
    __shared__ float sxT[Dv * Nv];                // SORTED order, transposed
    __shared__ float s_tw[Nv];                    // original order
    __shared__ float s_e[Nv];                     // sorted order
    __shared__ float s_ew[Nv];                    // sorted order
    __shared__ int   s_perm[Nv];                  // sorted pos -> original idx
    __shared__ int   s_wcnt[8][4];
    __shared__ int   s_woff[8][4];
    __shared__ int   s_tot[4];
    __shared__ int   s_base[5];                   // bucket segment starts
    __shared__ float warp_max[8][3];
    __shared__ float sm[Rv];

    const int b    = blockIdx.x;
    const int tid  = threadIdx.x;
    const int lane = tid & 31;
    const int wid  = tid >> 5;
    const size_t base = (size_t)b * Nv;

    // ================= Phase A: stage + counting sort by bucket =================
    #pragma unroll
    for (int i = tid; i < Rv * RSTRIDE; i += Nv) sPack[i] = g_pack[i];
    if (tid < Rv) sb2[tid] = g_b2[tid];
    {
        const float4* xb4 = (const float4*)(states + base * Dv);
        float4* sx4 = (float4*)sx;
        #pragma unroll
        for (int i = tid; i < (Nv * Dv) / 4; i += Nv) sx4[i] = xb4[i];
    }

    const int role = roles[base + tid];
    int mk;
    if (g_mask_is_u8) mk = ((const unsigned char*)maskp)[base + tid];
    else              mk = ((const int*)maskp)[base + tid];
    const bool act = (mk != 0);
    s_tw[tid] = trust[base + tid];

    const int bucket = act ? role : 3;
    const unsigned m0 = __ballot_sync(0xffffffffu, bucket == 0);
    const unsigned m1 = __ballot_sync(0xffffffffu, bucket == 1);
    const unsigned m2 = __ballot_sync(0xffffffffu, bucket == 2);
    const unsigned m3 = __ballot_sync(0xffffffffu, bucket == 3);
    if (lane == 0) {
        s_wcnt[wid][0] = __popc(m0);
        s_wcnt[wid][1] = __popc(m1);
        s_wcnt[wid][2] = __popc(m2);
        s_wcnt[wid][3] = __popc(m3);
    }
    __syncthreads();

    if (wid == 0) {
        if (lane < 4) {
            int off = 0;
            #pragma unroll
            for (int w = 0; w < 8; w++) { s_woff[w][lane] = off; off += s_wcnt[w][lane]; }
            s_tot[lane] = off;
        }
        __syncwarp();
        if (lane == 0) {
            s_base[0] = 0;
            #pragma unroll
            for (int r = 0; r < 4; r++) s_base[r + 1] = s_base[r] + s_tot[r];
        }
    }
    __syncthreads();

    {
        const unsigned mymask = (bucket == 0) ? m0 : (bucket == 1) ? m1 : (bucket == 2) ? m2 : m3;
        const unsigned lt = (1u << lane) - 1u;
        const int pos = s_base[bucket] + s_woff[wid][bucket] + __popc(mymask & lt);
        s_perm[pos] = tid;
    }
    __syncthreads();

    // ================= Phase B: MLP in sorted order (role-uniform warps) =========
    const int j = s_perm[tid];
    const int bkt = (tid >= s_base[3]) ? 3 : (tid >= s_base[2]) ? 2 : (tid >= s_base[1]) ? 1 : 0;

    float xj[Dv];
    #pragma unroll
    for (int d = 0; d < Dv; d++) {
        xj[d] = sx[j * Dv + d];          // gather
        sxT[d * Nv + tid] = xj[d];       // conflict-free transposed store (sorted)
    }

    float score = 0.0f;
    if (bkt < Rv) {                       // bucket-3 warps skip the MLP entirely
        const float4* wp = (const float4*)(sPack + bkt * RSTRIDE);
        float acc0 = 0.0f, acc1 = 0.0f;
        #pragma unroll
        for (int h = 0; h < Hv; h += 2) {
            const float4 a0 = wp[h * 2];       // warp-uniform broadcast
            const float4 c0 = wp[h * 2 + 1];
            const float4 a1 = wp[h * 2 + 2];
            const float4 c1 = wp[h * 2 + 3];
            float hv0 = fmaf(xj[0], a0.x, fmaf(xj[1], a0.y,
                        fmaf(xj[2], a0.z, fmaf(xj[3], a0.w,
                        fmaf(xj[4], c0.x, fmaf(xj[5], c0.y, c0.z))))));
            float hv1 = fmaf(xj[0], a1.x, fmaf(xj[1], a1.y,
                        fmaf(xj[2], a1.z, fmaf(xj[3], a1.w,
                        fmaf(xj[4], c1.x, fmaf(xj[5], c1.y, c1.z))))));
            acc0 = fmaf(fmaxf(hv0, 0.0f), c0.w, acc0);
            acc1 = fmaf(fmaxf(hv1, 0.0f), c1.w, acc1);
        }
        score = acc0 + acc1 + sb2[bkt];
    }

    // ---- per-role max (zeros included, matching reference semantics) ----
    float vm0 = 0.0f, vm1 = 0.0f, vm2 = 0.0f;
    if (bkt == 0)      vm0 = score;
    else if (bkt == 1) vm1 = score;
    else if (bkt == 2) vm2 = score;
    #pragma unroll
    for (int o = 16; o; o >>= 1) {
        vm0 = fmaxf(vm0, __shfl_xor_sync(0xffffffffu, vm0, o));
        vm1 = fmaxf(vm1, __shfl_xor_sync(0xffffffffu, vm1, o));
        vm2 = fmaxf(vm2, __shfl_xor_sync(0xffffffffu, vm2, o));
    }
    if (lane == 0) {
        warp_max[wid][0] = vm0;
        warp_max[wid][1] = vm1;
        warp_max[wid][2] = vm2;
    }
    __syncthreads();
    if (tid < Rv) {
        float m = warp_max[0][tid];
        #pragma unroll
        for (int w = 1; w < 8; w++) m = fmaxf(m, warp_max[w][tid]);
        sm[tid] = m;
    }
    __syncthreads();

    // ---- exponentials (sorted order) ----
    float e = 0.0f;
    if (bkt < Rv) e = __expf(score - sm[bkt]);
    s_e[tid]  = e;
    s_ew[tid] = e * s_tw[j];
    __syncthreads();

    // ================= Reduction: 3 warps, each over its contiguous segment ======
    if (wid < Rv) {
        const int r = wid;
        const int segLo = s_base[r], segHi = s_base[r + 1];
        float den = 0.0f, ws = 0.0f;
        float num[Dv] = {0.f, 0.f, 0.f, 0.f, 0.f, 0.f};
        for (int n0 = segLo; n0 < segHi; n0 += 32) {
            const int n = n0 + lane;
            if (n < segHi) {
                const float ev  = s_e[n];
                const float ewv = s_ew[n];
                den += ev;
                ws  += ewv;
                #pragma unroll
                for (int d = 0; d < Dv; d++)
                    num[d] = fmaf(ewv, sxT[d * Nv + n], num[d]);
            }
        }
        #pragma unroll
        for (int o = 16; o; o >>= 1) {
            den += __shfl_xor_sync(0xffffffffu, den, o);
            ws  += __shfl_xor_sync(0xffffffffu, ws,  o);
            #pragma unroll
            for (int d = 0; d < Dv; d++)
                num[d] += __shfl_xor_sync(0xffffffffu, num[d], o);
        }
        if (lane < Dv) {
            const float inv = 1.0f / (den + 1e-8f);
            const float wsv = fmaxf(ws * inv, 1e-8f);
            out[(size_t)b * (Rv * Dv) + r * Dv + lane] = num[lane] * inv / wsv;
        }
    }
}

extern "C" void kernel_launch(void* const* d_in, const int* in_sizes, int n_in,
                              void* d_out, int out_size) {
    const float* states = (const float*)d_in[0];
    const int*   roles  = (const int*)d_in[1];
    const void*  maskp  = d_in[2];
    const float* trust  = (const float*)d_in[3];
    const float* W1     = (const float*)d_in[4];
    const float* b1     = (const float*)d_in[5];
    const float* W2     = (const float*)d_in[6];
    const float* b2     = (const float*)d_in[7];
    float* out = (float*)d_out;

    prep_kernel<<<1, 256>>>(W1, b1, W2, b2, (const unsigned int*)maskp);
    hmf_encoder_kernel<<<Bv, Nv>>>(states, roles, maskp, trust, out);
}